// round 17
// baseline (speedup 1.0000x reference)
#include <cuda_runtime.h>
#include <cuda_bf16.h>
#include <cstdint>
#include <math.h>

// ---------------------------------------------------------------------------
// Problem constants (T=8, N=M=1024, H=8, D=256, NB = int(256*ln 256) = 1419)
// ---------------------------------------------------------------------------
#define TT   8
#define NPT  1024
#define HH   8
#define DDIM 256
#define NBF  1419
#define NBP  1472              // padded to multiple of 64
#define ROWS (TT * HH * NPT)   // 65536
#define BATCH (TT * HH)        // 64
#define HDCAT (HH * DDIM)      // 2048

#define DNORM   0.25f
#define DNORM2  0.0625f
#define EPSF    1e-4f
#define RATIO   0.026547529f   // 1/sqrt(1419)
#define SSCALE  68719476736.0  // 2^36 fixed-point scale for diag accumulation

typedef __nv_bfloat16 bf16;

// ---------------------------------------------------------------------------
// Scratch (device globals; zero-init at load -> never-written pads stay 0)
// ---------------------------------------------------------------------------
__device__ float g_qp[(size_t)ROWS * NBP];
__device__ float g_kp[(size_t)ROWS * NBP];
__device__ bf16 g_qin_h[(size_t)TT * NPT * DDIM],  g_qin_l[(size_t)TT * NPT * DDIM];
__device__ bf16 g_kin_h[(size_t)TT * NPT * DDIM],  g_kin_l[(size_t)TT * NPT * DDIM];
__device__ bf16 g_vin_h[(size_t)TT * NPT * DDIM],  g_vin_l[(size_t)TT * NPT * DDIM];
__device__ bf16 g_wtq_h[(size_t)HH * DDIM * DDIM], g_wtq_l[(size_t)HH * DDIM * DDIM];
__device__ bf16 g_wtk_h[(size_t)HH * DDIM * DDIM], g_wtk_l[(size_t)HH * DDIM * DDIM];
__device__ bf16 g_wtv_h[(size_t)HH * DDIM * DDIM], g_wtv_l[(size_t)HH * DDIM * DDIM];
__device__ bf16 g_pr_h[(size_t)NBP * DDIM],        g_pr_l[(size_t)NBP * DDIM];
__device__ bf16 g_wo_h[(size_t)DDIM * HDCAT],      g_wo_l[(size_t)DDIM * HDCAT];
__device__ bf16 g_qall_h[(size_t)ROWS * DDIM],     g_qall_l[(size_t)ROWS * DDIM];
__device__ bf16 g_kall_h[(size_t)ROWS * DDIM],     g_kall_l[(size_t)ROWS * DDIM];
__device__ bf16 g_vt_h[(size_t)ROWS * DDIM],       g_vt_l[(size_t)ROWS * DDIM];
__device__ bf16 g_qph[(size_t)ROWS * NBP],         g_qpl[(size_t)ROWS * NBP];
__device__ bf16 g_kpT_h[(size_t)BATCH * NBP * NPT], g_kpT_l[(size_t)BATCH * NBP * NPT];
__device__ bf16 g_ctxT_h[(size_t)BATCH * DDIM * NBP], g_ctxT_l[(size_t)BATCH * DDIM * NBP];
__device__ bf16 g_outs_h[(size_t)TT * NPT * HDCAT], g_outs_l[(size_t)TT * NPT * HDCAT];
__device__ float g_ksum[(size_t)BATCH * NBP];
__device__ float g_kpart[(size_t)BATCH * 8 * NBP];
__device__ float g_dinv[(size_t)ROWS];
__device__ unsigned g_kmaxu[(size_t)BATCH];
__device__ unsigned g_rowmaxu[(size_t)ROWS];
__device__ unsigned long long g_dq64[(size_t)ROWS];
__device__ unsigned long long g_dk64[(size_t)ROWS];

// second operand/output set for merged launches
struct Dual {
    const bf16 *a2h, *a2l, *b2h, *b2l;
    float* cf2;
    bf16 *c2h, *c2l;
    const float* bias2;
    unsigned* maxu2;
    unsigned long long* sacc2;
};

// ---------------------------------------------------------------------------
// helpers
// ---------------------------------------------------------------------------
__device__ __forceinline__ uint32_t smem_u32(const void* p) {
    uint32_t a;
    asm("{ .reg .u64 t; cvta.to.shared.u64 t, %1; cvt.u32.u64 %0, t; }"
        : "=r"(a) : "l"(p));
    return a;
}

__device__ __forceinline__ void ldm4(uint32_t& r0, uint32_t& r1,
                                     uint32_t& r2, uint32_t& r3, uint32_t a) {
    asm volatile("ldmatrix.sync.aligned.m8n8.x4.shared.b16 {%0,%1,%2,%3}, [%4];"
                 : "=r"(r0), "=r"(r1), "=r"(r2), "=r"(r3) : "r"(a));
}

__device__ __forceinline__ void mma16816(float* c, uint32_t a0, uint32_t a1,
                                         uint32_t a2, uint32_t a3,
                                         uint32_t b0, uint32_t b1) {
    asm volatile(
        "mma.sync.aligned.m16n8k16.row.col.f32.bf16.bf16.f32 "
        "{%0,%1,%2,%3},{%4,%5,%6,%7},{%8,%9},{%0,%1,%2,%3};"
        : "+f"(c[0]), "+f"(c[1]), "+f"(c[2]), "+f"(c[3])
        : "r"(a0), "r"(a1), "r"(a2), "r"(a3), "r"(b0), "r"(b1));
}

__device__ __forceinline__ void cpasync16(uint32_t dst, const bf16* src, int sz) {
    asm volatile("cp.async.cg.shared.global [%0], [%1], 16, %2;"
                 :: "r"(dst), "l"(__cvta_generic_to_global(src)), "r"(sz));
}

__device__ __forceinline__ void splitw(float x, bf16& h, bf16& l) {
    h = __float2bfloat16_rn(x);
    l = __float2bfloat16_rn(x - __bfloat162float(h));
}

__device__ __forceinline__ uint32_t packbf(bf16 a, bf16 b) {
    return (uint32_t)__bfloat16_as_ushort(a)
         | ((uint32_t)__bfloat16_as_ushort(b) << 16);
}

__device__ __forceinline__ void split2p(float x, float y,
                                        uint32_t& ph, uint32_t& pl) {
    bf16 hx, lx, hy, ly;
    splitw(x, hx, lx); splitw(y, hy, ly);
    ph = packbf(hx, hy); pl = packbf(lx, ly);
}

__device__ __forceinline__ unsigned encf(float f) {
    unsigned u = __float_as_uint(f);
    return (u & 0x80000000u) ? ~u : (u | 0x80000000u);
}
__device__ __forceinline__ float decf(unsigned u) {
    unsigned b = (u & 0x80000000u) ? (u ^ 0x80000000u) : ~u;
    return __uint_as_float(b);
}

__device__ __forceinline__ float diag_from_i64(unsigned long long v) {
    return 0.5f * DNORM2 * (float)((double)(long long)v * (1.0 / SSCALE));
}

// ---------------------------------------------------------------------------
// gemm7: NT bf16x3 mma.sync GEMM, 256 threads, 8 warps (4m x 2n), 32x32/warp,
//        CTA tile 128x64, 3-stage cp.async ring (ONE sync/stage), 2 CTAs/SM.
//   C[M,N] = A[M,K] * B[N,K]^T ; operands hi/lo bf16, k-contiguous.
//   EPI: 1 +bias[col] f32 | 2 *scale[row] bf16 pair | 4 plain bf16 pair
//        7 +bias[row] bf16 pair
//        9 merged dash: z<zSplit -> f32 + row-max | z>=zSplit -> dual A/C set,
//          f32 + slab-max  (B operand shared)
//       10 merged proj: +bias[col] bf16 pair + row-sumsq i64; dual set for
//          z>=zSplit
//   K % 32 == 0, N even, lda == ldb == K.
// ---------------------------------------------------------------------------
#define TSTRIDE 40
#define AT_B 10240
#define BT_B 5120
#define STAGE_B 30720
#define G7SMEM  (3 * STAGE_B)   // 92160 bytes, 3-stage ring

template<int EPI>
__global__ void __launch_bounds__(256, 2)
gemm7(const bf16* __restrict__ Ahi, const bf16* __restrict__ Alo,
      const bf16* __restrict__ Bhi, const bf16* __restrict__ Blo,
      float* __restrict__ Cf, bf16* __restrict__ Chi, bf16* __restrict__ Clo,
      int M, int N, int K, int lda, int ldb, int ldc,
      long aT, long aH, long bT, long bH, long cT, long cH, int Hdiv,
      const float* __restrict__ bias, long biasH,
      const float* __restrict__ scale, long scT, long scH,
      unsigned* __restrict__ maxu, int vlim,
      unsigned long long* __restrict__ sacc,
      Dual dp, int zSplit)
{
    extern __shared__ bf16 smb[];
    const uint32_t sb = smem_u32(smb);
    const int tid = threadIdx.x;
    const int wid = tid >> 5, lane = tid & 31;
    const int warp_m = wid >> 1, warp_n = wid & 1;
    const int g = lane >> 2, tg = lane & 3;

    const bool second = (EPI == 9 || EPI == 10) && ((int)blockIdx.z >= zSplit);
    const int bz = second ? (int)blockIdx.z - zSplit : (int)blockIdx.z;
    const int t = bz / Hdiv, h = bz % Hdiv;
    const long aoff = (long)t * aT + (long)h * aH;
    const long boff = (long)t * bT + (long)h * bH;
    const long coff = (long)t * cT + (long)h * cH;

    const bf16* srcAh = (second ? dp.a2h : Ahi) + aoff;
    const bf16* srcAl = (second ? dp.a2l : Alo) + aoff;
    const bf16* srcBh = ((EPI == 10 && second) ? dp.b2h : Bhi) + boff;
    const bf16* srcBl = ((EPI == 10 && second) ? dp.b2l : Blo) + boff;
    float* Cfp = (EPI == 9 && second) ? dp.cf2 : Cf;
    bf16* Chip = (EPI == 10 && second) ? dp.c2h : Chi;
    bf16* Clop = (EPI == 10 && second) ? dp.c2l : Clo;
    const float* biasb = (EPI == 10 && second) ? dp.bias2 : bias;
    unsigned long long* saccp = (EPI == 10 && second) ? dp.sacc2 : sacc;

    const float* biasp  = (EPI == 1 || EPI == 7 || EPI == 10)
                        ? biasb + (long)h * biasH : nullptr;
    const float* scalep = (EPI == 2) ? scale + (long)t * scT + (long)h * scH : nullptr;

    const int m0 = blockIdx.y * 128;
    const int n0 = blockIdx.x * 64;

    const int S = K >> 5;

    auto stage = [&](int s, int bi) {
        const int k0 = s << 5;
        const uint32_t base = sb + (uint32_t)bi * STAGE_B;
#pragma unroll
        for (int c = 0; c < 2; c++) {
            const int id = tid + c * 256;
            const int r = id >> 2, q = id & 3;
            const int gr = m0 + r;
            const int sz = (gr < M) ? 16 : 0;
            const long so = (long)(sz ? gr : m0) * lda + k0 + q * 8;
            const uint32_t d = base + (uint32_t)(r * TSTRIDE + q * 8) * 2;
            cpasync16(d, srcAh + so, sz);
            cpasync16(d + AT_B, srcAl + so, sz);
        }
        {
            const int r = tid >> 2, q = tid & 3;
            const int gr = n0 + r;
            const int sz = (gr < N) ? 16 : 0;
            const long so = (long)(sz ? gr : n0) * ldb + k0 + q * 8;
            const uint32_t d = base + (uint32_t)(2 * AT_B)
                             + (uint32_t)(r * TSTRIDE + q * 8) * 2;
            cpasync16(d, srcBh + so, sz);
            cpasync16(d + BT_B, srcBl + so, sz);
        }
        asm volatile("cp.async.commit_group;" ::: "memory");
    };

    float acc[2][4][4];
#pragma unroll
    for (int i = 0; i < 2; i++)
#pragma unroll
        for (int j = 0; j < 4; j++)
#pragma unroll
            for (int e = 0; e < 4; e++) acc[i][j][e] = 0.f;

    stage(0, 0);
    if (S > 1) stage(1, 1);

    for (int s = 0; s < S; s++) {
        // wait for stage s (keep at most 1 younger group in flight)
        if (s + 1 < S) asm volatile("cp.async.wait_group 1;" ::: "memory");
        else           asm volatile("cp.async.wait_group 0;" ::: "memory");
        __syncthreads();

        // stage s+2 into ring slot (s+2)%3 — not read this iter, no 2nd sync
        if (s + 2 < S) stage(s + 2, (s + 2) % 3);

        const uint32_t base = sb + (uint32_t)(s % 3) * STAGE_B;
#pragma unroll
        for (int ks = 0; ks < 2; ks++) {
            const int ko = ks << 4;
            uint32_t bh[4][2], bl[4][2];
#pragma unroll
            for (int p = 0; p < 2; p++) {
                const int nrow = warp_n * 32 + p * 16 + ((lane >> 4) << 3) + (lane & 7);
                const int kcol = ko + ((lane >> 3) & 1) * 8;
                const uint32_t ab = base + (uint32_t)(2 * AT_B)
                                  + (uint32_t)(nrow * TSTRIDE + kcol) * 2;
                ldm4(bh[2 * p][0], bh[2 * p][1], bh[2 * p + 1][0], bh[2 * p + 1][1], ab);
                ldm4(bl[2 * p][0], bl[2 * p][1], bl[2 * p + 1][0], bl[2 * p + 1][1],
                     ab + BT_B);
            }
#pragma unroll
            for (int ma = 0; ma < 2; ma++) {
                const int mrow = warp_m * 32 + ma * 16 + ((lane >> 3) & 1) * 8 + (lane & 7);
                const int kcol = ko + (lane >> 4) * 8;
                const uint32_t aa = base + (uint32_t)(mrow * TSTRIDE + kcol) * 2;
                uint32_t ah0, ah1, ah2, ah3, al0, al1, al2, al3;
                ldm4(ah0, ah1, ah2, ah3, aa);
                ldm4(al0, al1, al2, al3, aa + AT_B);
#pragma unroll
                for (int nb = 0; nb < 4; nb++) {
                    mma16816(acc[ma][nb], ah0, ah1, ah2, ah3, bh[nb][0], bh[nb][1]);
                    mma16816(acc[ma][nb], ah0, ah1, ah2, ah3, bl[nb][0], bl[nb][1]);
                    mma16816(acc[ma][nb], al0, al1, al2, al3, bh[nb][0], bh[nb][1]);
                }
            }
        }
    }

    // ---- epilogue (N even; col and col+1 in-bounds together)
    float slabmax = -3.4e38f;
#pragma unroll
    for (int ma = 0; ma < 2; ma++) {
#pragma unroll
        for (int hf = 0; hf < 2; hf++) {
            const int row = m0 + warp_m * 32 + ma * 16 + g + hf * 8;
            float rowmax = -3.4e38f;
            float ss = 0.f;
            const bool rok = row < M;
            const float sc = (EPI == 2 && rok) ? scalep[row] : 1.f;
            const float rb = (EPI == 7 && rok) ? biasp[row] : 0.f;
#pragma unroll
            for (int nb = 0; nb < 4; nb++) {
                const int col = n0 + warp_n * 32 + nb * 8 + 2 * tg;
                if (!rok || col >= N) continue;
                float v0 = acc[ma][nb][hf * 2 + 0];
                float v1 = acc[ma][nb][hf * 2 + 1];
                if (EPI == 1 || EPI == 10) { v0 += biasp[col]; v1 += biasp[col + 1]; }
                if (EPI == 7) { v0 += rb; v1 += rb; }
                if (EPI == 2) { v0 *= sc; v1 *= sc; }
                if (EPI == 10) ss += v0 * v0 + v1 * v1;
                const long idx = coff + (long)row * ldc + col;
                if (EPI == 1 || EPI == 9) {
                    *(float2*)&Cfp[idx] = make_float2(v0, v1);
                    if (EPI == 9) {
                        if (col < vlim) {
                            if (second) slabmax = fmaxf(slabmax, v0);
                            else        rowmax  = fmaxf(rowmax, v0);
                        }
                        if (col + 1 < vlim) {
                            if (second) slabmax = fmaxf(slabmax, v1);
                            else        rowmax  = fmaxf(rowmax, v1);
                        }
                    }
                } else {
                    uint32_t ph, pl;
                    split2p(v0, v1, ph, pl);
                    *(uint32_t*)&Chip[idx] = ph;
                    *(uint32_t*)&Clop[idx] = pl;
                }
            }
            if (EPI == 9 && !second) {
                rowmax = fmaxf(rowmax, __shfl_xor_sync(0xffffffffu, rowmax, 1));
                rowmax = fmaxf(rowmax, __shfl_xor_sync(0xffffffffu, rowmax, 2));
                if (tg == 0 && rok)
                    atomicMax(&maxu[(long)bz * M + row], encf(rowmax));
            }
            if (EPI == 10) {
                ss += __shfl_xor_sync(0xffffffffu, ss, 1);
                ss += __shfl_xor_sync(0xffffffffu, ss, 2);
                if (tg == 0 && rok)
                    atomicAdd(&saccp[(long)bz * M + row],
                              (unsigned long long)(long long)((double)ss * SSCALE));
            }
        }
    }
    if (EPI == 9 && second) {
#pragma unroll
        for (int o = 16; o > 0; o >>= 1)
            slabmax = fmaxf(slabmax, __shfl_xor_sync(0xffffffffu, slabmax, o));
        if (lane == 0) atomicMax(&dp.maxu2[bz], encf(slabmax));
    }
}

// ---------------------------------------------------------------------------
// conversion / reset passes
// ---------------------------------------------------------------------------
__global__ void reset_k(unsigned* __restrict__ kmaxu, unsigned* __restrict__ rowmaxu,
                        unsigned long long* __restrict__ dq,
                        unsigned long long* __restrict__ dk)
{
    int i = blockIdx.x * blockDim.x + threadIdx.x;
    if (i < BATCH) kmaxu[i] = 0u;
    if (i < ROWS) { rowmaxu[i] = 0u; dq[i] = 0ull; dk[i] = 0ull; }
}

// merged q/k/v input split: 8 elems/thread, blockIdx.y selects tensor
__global__ void splitin_k(const float* __restrict__ q, const float* __restrict__ k,
                          const float* __restrict__ v,
                          bf16* __restrict__ qh, bf16* __restrict__ ql,
                          bf16* __restrict__ kh, bf16* __restrict__ kl,
                          bf16* __restrict__ vh, bf16* __restrict__ vl,
                          size_t n)
{
    const int which = blockIdx.y;
    const float* s = (which == 0) ? q : (which == 1) ? k : v;
    bf16* h = (which == 0) ? qh : (which == 1) ? kh : vh;
    bf16* l = (which == 0) ? ql : (which == 1) ? kl : vl;
    size_t i8 = ((size_t)blockIdx.x * blockDim.x + threadIdx.x) * 8;
    if (i8 < n) {
        float4 x0 = *(const float4*)(s + i8);
        float4 x1 = *(const float4*)(s + i8 + 4);
        uint32_t ph0, pl0, ph1, pl1, ph2, pl2, ph3, pl3;
        split2p(x0.x, x0.y, ph0, pl0);
        split2p(x0.z, x0.w, ph1, pl1);
        split2p(x1.x, x1.y, ph2, pl2);
        split2p(x1.z, x1.w, ph3, pl3);
        *(uint4*)(h + i8) = make_uint4(ph0, ph1, ph2, ph3);
        *(uint4*)(l + i8) = make_uint4(pl0, pl1, pl2, pl3);
    }
}

// generic split (proj): 8 elems/thread (n % 8 == 0)
__global__ void split_k(const float* __restrict__ s, bf16* __restrict__ h,
                        bf16* __restrict__ l, size_t n, float scl)
{
    size_t i8 = ((size_t)blockIdx.x * blockDim.x + threadIdx.x) * 8;
    if (i8 < n) {
        float4 x0 = *(const float4*)(s + i8);
        float4 x1 = *(const float4*)(s + i8 + 4);
        uint32_t ph0, pl0, ph1, pl1, ph2, pl2, ph3, pl3;
        split2p(x0.x * scl, x0.y * scl, ph0, pl0);
        split2p(x0.z * scl, x0.w * scl, ph1, pl1);
        split2p(x1.x * scl, x1.y * scl, ph2, pl2);
        split2p(x1.z * scl, x1.w * scl, ph3, pl3);
        *(uint4*)(h + i8) = make_uint4(ph0, ph1, ph2, ph3);
        *(uint4*)(l + i8) = make_uint4(pl0, pl1, pl2, pl3);
    }
}

__global__ void wsplit_k(const float* __restrict__ W, bf16* __restrict__ h,
                         bf16* __restrict__ l)
{
    int i = blockIdx.x * blockDim.x + threadIdx.x;
    if (i < DDIM * HDCAT) {
        int d = i / HDCAT, fp = i % HDCAT;
        int hh = fp >> 8, e = fp & 255;
        float x = W[(size_t)d * HDCAT + e * 8 + hh];
        bf16 hb, lb; splitw(x, hb, lb);
        h[i] = hb; l[i] = lb;
    }
}

// merged weight transpose-split: z in [0, 3*HH); z/HH selects Wq/Wk/Wv
__global__ void tsplit3_k(const float* __restrict__ Wq, const float* __restrict__ Wk,
                          const float* __restrict__ Wv,
                          bf16* __restrict__ qh, bf16* __restrict__ ql,
                          bf16* __restrict__ kh, bf16* __restrict__ kl,
                          bf16* __restrict__ vh, bf16* __restrict__ vl)
{
    __shared__ float sm[32][33];
    const int zz = blockIdx.z;
    const int which = zz / HH, z = zz % HH;
    const float* W = (which == 0) ? Wq : (which == 1) ? Wk : Wv;
    bf16* hi = (which == 0) ? qh : (which == 1) ? kh : vh;
    bf16* lo = (which == 0) ? ql : (which == 1) ? kl : vl;
    const int R = DDIM, C = DDIM;
    const int c0 = blockIdx.x * 32, r0 = blockIdx.y * 32;
    const float* s = W + (size_t)z * R * C;
    bf16* ho = hi + (size_t)z * R * C;
    bf16* lv = lo + (size_t)z * R * C;
    const int tx = threadIdx.x, ty = threadIdx.y;
    for (int i = ty; i < 32; i += 8)
        sm[i][tx] = s[(size_t)(r0 + i) * C + c0 + tx];
    __syncthreads();
    for (int i = ty; i < 32; i += 8) {
        float x = sm[tx][i];
        bf16 hb, lb; splitw(x, hb, lb);
        ho[(size_t)(c0 + i) * R + r0 + tx] = hb;
        lv[(size_t)(c0 + i) * R + r0 + tx] = lb;
    }
}

// ---------------------------------------------------------------------------
// feature-map / reduction kernels
// ---------------------------------------------------------------------------
__global__ void __launch_bounds__(256)
qexp2_k(const float* __restrict__ qp, const unsigned long long* __restrict__ dq,
        const unsigned* __restrict__ rowmaxu,
        const float* __restrict__ ksum, bf16* __restrict__ oh,
        bf16* __restrict__ ol, float* __restrict__ dinv)
{
    const size_t r = blockIdx.x;
    const int b = (int)(r >> 10);
    const float* prow = qp + r * NBP;
    const float* ks = ksum + (size_t)b * NBP;
    const int tid = threadIdx.x;
    const int wid = tid >> 5, lane = tid & 31;
    __shared__ float wred[8];

    const float c = diag_from_i64(dq[r]) + decf(rowmaxu[r]);

    float dot = 0.f;
    for (int j = tid * 4; j < NBP; j += 1024) {
        float4 p = *(const float4*)(prow + j);
        float v0 = (j + 0 < NBF) ? RATIO * (__expf(p.x - c) + EPSF) : 0.f;
        float v1 = (j + 1 < NBF) ? RATIO * (__expf(p.y - c) + EPSF) : 0.f;
        float v2 = (j + 2 < NBF) ? RATIO * (__expf(p.z - c) + EPSF) : 0.f;
        float v3 = (j + 3 < NBF) ? RATIO * (__expf(p.w - c) + EPSF) : 0.f;
        uint32_t ph0, pl0, ph1, pl1;
        split2p(v0, v1, ph0, pl0);
        split2p(v2, v3, ph1, pl1);
        *(uint2*)(oh + r * NBP + j) = make_uint2(ph0, ph1);
        *(uint2*)(ol + r * NBP + j) = make_uint2(pl0, pl1);
        float4 kv = *(const float4*)(ks + j);
        dot += v0 * kv.x + v1 * kv.y + v2 * kv.z + v3 * kv.w;
    }
#pragma unroll
    for (int o = 16; o > 0; o >>= 1)
        dot += __shfl_xor_sync(0xffffffffu, dot, o);
    if (lane == 0) wred[wid] = dot;
    __syncthreads();
    if (tid == 0) {
        float s = wred[0];
#pragma unroll
        for (int i = 1; i < 8; i++) s += wred[i];
        dinv[r] = 1.0f / s;
    }
}

__global__ void __launch_bounds__(256)
ktexp_k(const float* __restrict__ kp, const unsigned long long* __restrict__ dk,
        const unsigned* __restrict__ kmaxu, bf16* __restrict__ th,
        bf16* __restrict__ tl, float* __restrict__ part)
{
    __shared__ float sm[32][132];
    const int b = blockIdx.z;
    const int m0 = blockIdx.x * 32, n0 = blockIdx.y * 128;
    const int tid = threadIdx.x;
    const float km = decf(kmaxu[b]);

    {
        const int n = tid >> 1, half = tid & 1;
        const float dkv = diag_from_i64(dk[(size_t)b * NPT + n0 + n]);
        const float* src = kp + ((size_t)b * NPT + n0 + n) * NBP + m0 + half * 16;
#pragma unroll
        for (int c4 = 0; c4 < 4; c4++) {
            float4 xx = *(const float4*)(src + c4 * 4);
            const int mb = m0 + half * 16 + c4 * 4;
            float vv[4] = {xx.x, xx.y, xx.z, xx.w};
#pragma unroll
            for (int e = 0; e < 4; e++)
                sm[half * 16 + c4 * 4 + e][n] =
                    (mb + e < NBF) ? RATIO * (__expf(vv[e] - dkv - km) + EPSF) : 0.f;
        }
    }
    __syncthreads();

    {
        const int w = tid >> 5, lane = tid & 31;
#pragma unroll
        for (int i = 0; i < 4; i++) {
            const int m = w * 4 + i;
            float4 v = *(const float4*)&sm[m][4 * lane];
            uint32_t ph0, pl0, ph1, pl1;
            split2p(v.x, v.y, ph0, pl0);
            split2p(v.z, v.w, ph1, pl1);
            const size_t obase = ((size_t)b * NBP + m0 + m) * NPT + n0 + 4 * lane;
            *(uint2*)&th[obase] = make_uint2(ph0, ph1);
            *(uint2*)&tl[obase] = make_uint2(pl0, pl1);
            float s = v.x + v.y + v.z + v.w;
#pragma unroll
            for (int o = 16; o > 0; o >>= 1)
                s += __shfl_xor_sync(0xffffffffu, s, o);
            if (lane == 0)
                part[((size_t)b * 8 + blockIdx.y) * NBP + m0 + m] = s;
        }
    }
}

__global__ void ksum2_k(const float* __restrict__ part, float* __restrict__ ksum)
{
    const int b = blockIdx.y;
    const int m = blockIdx.x * blockDim.x + threadIdx.x;
    if (m >= NBP) return;
    float s = 0.f;
#pragma unroll
    for (int j = 0; j < 8; j++)
        s += part[((size_t)b * 8 + j) * NBP + m];
    ksum[(size_t)b * NBP + m] = s;
}

// ---------------------------------------------------------------------------
// Launch
// ---------------------------------------------------------------------------
#define GETP(var, sym) cudaGetSymbolAddress((void**)&var, sym)

extern "C" void kernel_launch(void* const* d_in, const int* in_sizes, int n_in,
                              void* d_out, int out_size)
{
    const float* q     = (const float*)d_in[0];
    const float* k     = (const float*)d_in[1];
    const float* v     = (const float*)d_in[2];
    const float* Wq    = (const float*)d_in[3];
    const float* bq    = (const float*)d_in[4];
    const float* Wk    = (const float*)d_in[5];
    const float* bk    = (const float*)d_in[6];
    const float* Wv    = (const float*)d_in[7];
    const float* bv    = (const float*)d_in[8];
    const float* W_out = (const float*)d_in[9];
    const float* b_out = (const float*)d_in[10];
    const float* proj  = (const float*)d_in[11];
    float* out = (float*)d_out;

    float *qp, *kp, *ksum, *kpart, *dinv;
    unsigned *kmaxu, *rowmaxu;
    unsigned long long *dq64, *dk64;
    bf16 *qin_h, *qin_l, *kin_h, *kin_l, *vin_h, *vin_l;
    bf16 *wtq_h, *wtq_l, *wtk_h, *wtk_l, *wtv_h, *wtv_l;
    bf16 *pr_h, *pr_l, *wo_h, *wo_l;
    bf16 *qall_h, *qall_l, *kall_h, *kall_l, *vt_h, *vt_l;
    bf16 *qph, *qpl, *kpT_h, *kpT_l, *ctxT_h, *ctxT_l, *outs_h, *outs_l;

    GETP(qp, g_qp); GETP(kp, g_kp);
    GETP(qin_h, g_qin_h); GETP(qin_l, g_qin_l);
    GETP(kin_h, g_kin_h); GETP(kin_l, g_kin_l);
    GETP(vin_h, g_vin_h); GETP(vin_l, g_vin_l);
    GETP(wtq_h, g_wtq_h); GETP(wtq_l, g_wtq_l);
    GETP(wtk_h, g_wtk_h); GETP(wtk_l, g_wtk_l);
    GETP(wtv_h, g_wtv_h); GETP(wtv_l, g_wtv_l);
    GETP(pr_h, g_pr_h);   GETP(pr_l, g_pr_l);
    GETP(wo_h, g_wo_h);   GETP(wo_l, g_wo_l);
    GETP(qall_h, g_qall_h); GETP(qall_l, g_qall_l);
    GETP(kall_h, g_kall_h); GETP(kall_l, g_kall_l);
    GETP(vt_h, g_vt_h);     GETP(vt_l, g_vt_l);
    GETP(qph, g_qph);       GETP(qpl, g_qpl);
    GETP(kpT_h, g_kpT_h);   GETP(kpT_l, g_kpT_l);
    GETP(ctxT_h, g_ctxT_h); GETP(ctxT_l, g_ctxT_l);
    GETP(outs_h, g_outs_h); GETP(outs_l, g_outs_l);
    GETP(ksum, g_ksum); GETP(kpart, g_kpart);
    GETP(dinv, g_dinv); GETP(kmaxu, g_kmaxu); GETP(rowmaxu, g_rowmaxu);
    GETP(dq64, g_dq64); GETP(dk64, g_dk64);

    cudaFuncSetAttribute(gemm7<1>,  cudaFuncAttributeMaxDynamicSharedMemorySize, G7SMEM);
    cudaFuncSetAttribute(gemm7<2>,  cudaFuncAttributeMaxDynamicSharedMemorySize, G7SMEM);
    cudaFuncSetAttribute(gemm7<4>,  cudaFuncAttributeMaxDynamicSharedMemorySize, G7SMEM);
    cudaFuncSetAttribute(gemm7<7>,  cudaFuncAttributeMaxDynamicSharedMemorySize, G7SMEM);
    cudaFuncSetAttribute(gemm7<9>,  cudaFuncAttributeMaxDynamicSharedMemorySize, G7SMEM);
    cudaFuncSetAttribute(gemm7<10>, cudaFuncAttributeMaxDynamicSharedMemorySize, G7SMEM);

    Dual d0 = {};

    // ---- 0) reset accumulators (graph replays!) + operand splits
    reset_k<<<(ROWS + 255) / 256, 256>>>(kmaxu, rowmaxu, dq64, dk64);
    {
        const size_t nin = (size_t)TT * NPT * DDIM;
        dim3 sg((unsigned)((nin / 8 + 255) / 256), 3);
        splitin_k<<<sg, 256>>>(q, k, v, qin_h, qin_l, kin_h, kin_l,
                               vin_h, vin_l, nin);
        dim3 tg(8, 8, 3 * HH), tb(32, 8);
        tsplit3_k<<<tg, tb>>>(Wq, Wk, Wv, wtq_h, wtq_l, wtk_h, wtk_l,
                              wtv_h, wtv_l);
        const size_t npr = (size_t)NBF * DDIM;
        split_k<<<(unsigned)((npr / 8 + 255) / 256), 256>>>(proj, pr_h, pr_l, npr, DNORM);
        wsplit_k<<<(DDIM * HDCAT + 255) / 256, 256>>>(W_out, wo_h, wo_l);
    }

    // ---- 1) merged q+k projections (EPI 10; z<64 -> q, z>=64 -> k)
    {
        Dual dk_ = d0;
        dk_.a2h = kin_h; dk_.a2l = kin_l;
        dk_.b2h = wtk_h; dk_.b2l = wtk_l;
        dk_.c2h = kall_h; dk_.c2l = kall_l;
        dk_.bias2 = bk; dk_.sacc2 = dk64;
        dim3 grid(4, 8, 2 * BATCH);
        gemm7<10><<<grid, 256, G7SMEM>>>(qin_h, qin_l, wtq_h, wtq_l,
            nullptr, qall_h, qall_l,
            NPT, DDIM, DDIM, DDIM, DDIM, DDIM,
            (long)NPT * DDIM, 0, 0, (long)DDIM * DDIM,
            (long)HH * NPT * DDIM, (long)NPT * DDIM, HH,
            bq, DDIM, nullptr, 0, 0, nullptr, 0, dq64, dk_, BATCH);
    }
    // v projection directly transposed: vt[b][e][n] (EPI 7: row bias)
    {
        dim3 grid(NPT / 64, 2, BATCH);
        gemm7<7><<<grid, 256, G7SMEM>>>(wtv_h, wtv_l, vin_h, vin_l,
            nullptr, vt_h, vt_l,
            DDIM, NPT, DDIM, DDIM, DDIM, NPT,
            0, (long)DDIM * DDIM, (long)NPT * DDIM, 0,
            (long)HH * DDIM * NPT, (long)DDIM * NPT, HH,
            bv, DDIM, nullptr, 0, 0, nullptr, 0, nullptr, d0, 1 << 30);
    }

    // ---- 2) merged dash (EPI 9; z<64 -> q rows+rowmax, z>=64 -> k+slabmax)
    {
        Dual dd = d0;
        dd.a2h = kall_h; dd.a2l = kall_l;
        dd.cf2 = kp; dd.maxu2 = kmaxu;
        dim3 grid(NBP / 64, 8, 2 * BATCH);
        gemm7<9><<<grid, 256, G7SMEM>>>(qall_h, qall_l, pr_h, pr_l,
            qp, nullptr, nullptr,
            NPT, NBP, DDIM, DDIM, DDIM, NBP,
            (long)NPT * DDIM, 0, 0, 0, (long)NPT * NBP, 0, 1,
            nullptr, 0, nullptr, 0, 0, rowmaxu, NBF, nullptr, dd, BATCH);
    }

    // ---- 3) k-side feature map chain, then fused q-exp + d_inv
    ktexp_k<<<dim3(NBP / 32, 8, BATCH), 256>>>(kp, dk64, kmaxu, kpT_h, kpT_l, kpart);
    ksum2_k<<<dim3((NBP + 255) / 256, BATCH), 256>>>(kpart, ksum);
    qexp2_k<<<ROWS, 256>>>(qp, dq64, rowmaxu, ksum, qph, qpl, dinv);

    // ---- 4) ctxT[b][e][m] = vt[b] * kpT[b]^T (per-slab: Hdiv = 1)
    {
        dim3 grid(NBP / 64, 2, BATCH);
        gemm7<4><<<grid, 256, G7SMEM>>>(vt_h, vt_l, kpT_h, kpT_l,
            nullptr, ctxT_h, ctxT_l,
            DDIM, NBP, NPT, NPT, NPT, NBP,
            (long)DDIM * NPT, 0, (long)NBP * NPT, 0, (long)DDIM * NBP, 0, 1,
            nullptr, 0, nullptr, 0, 0, nullptr, 0, nullptr, d0, 1 << 30);
    }

    // ---- 5) out: [t][n][h*256+e] contiguous bf16-pair store, *dinv (Hdiv = HH)
    {
        dim3 grid(4, 8, BATCH);
        gemm7<2><<<grid, 256, G7SMEM>>>(qph, qpl, ctxT_h, ctxT_l,
            nullptr, outs_h, outs_l,
            NPT, DDIM, NBP, NBP, NBP, HDCAT,
            (long)HH * NPT * NBP, (long)NPT * NBP,
            (long)HH * DDIM * NBP, (long)DDIM * NBP,
            (long)NPT * HDCAT, (long)DDIM, HH,
            nullptr, 0, dinv, (long)HH * NPT, (long)NPT, nullptr, 0, nullptr,
            d0, 1 << 30);
    }

    // ---- 6) final: rep[8192][256] = outs * wr^T + b_out (wr = permuted W_out)
    {
        dim3 grid(4, 64, 1);
        gemm7<1><<<grid, 256, G7SMEM>>>(outs_h, outs_l, wo_h, wo_l,
            out, nullptr, nullptr,
            TT * NPT, DDIM, HDCAT, HDCAT, HDCAT, DDIM,
            0, 0, 0, 0, 0, 0, 1,
            b_out, 0, nullptr, 0, 0, nullptr, 0, nullptr, d0, 1 << 30);
    }
}